// round 4
// baseline (speedup 1.0000x reference)
#include <cuda_runtime.h>
#include <cstdint>
#include <cstddef>

#define L_ 8
#define M_ 128
#define K_ 32
#define D_ 16
#define B_ 2048
#define N_ 1024  /* L_*M_ */

#define XT_OFF   0u
#define TR_OFF   ((unsigned)(D_ * B_))
#define OUT_OFF  ((unsigned)(D_ * B_ + N_ * D_ * B_))

static __device__ float g_scratch[(size_t)D_ * B_ + 2ull * N_ * D_ * B_];

// ---- packed fp32x2 helpers (sm_10x only) ----------------------------------
__device__ __forceinline__ unsigned long long fma2(
    unsigned long long a, unsigned long long b, unsigned long long c)
{
    unsigned long long d;
    asm("fma.rn.f32x2 %0, %1, %2, %3;" : "=l"(d) : "l"(a), "l"(b), "l"(c));
    return d;
}
__device__ __forceinline__ unsigned long long pack2(float lo, float hi)
{
    unsigned long long r;
    asm("mov.b64 %0, {%1, %2};" : "=l"(r) : "f"(lo), "f"(hi));
    return r;
}
__device__ __forceinline__ float2 unpack2(unsigned long long v)
{
    float2 r;
    asm("mov.b64 {%0, %1}, %2;" : "=f"(r.x), "=f"(r.y) : "l"(v));
    return r;
}

// ---------------------------------------------------------------------------
// Transpose: block = (node, half-of-B).  One (1024, D) half-tile -> (D, 1024).
// ---------------------------------------------------------------------------
__global__ void __launch_bounds__(256) transpose_kernel(
    const float* __restrict__ trace, const float* __restrict__ x)
{
    __shared__ float tile[128 * 17];
    const int blk  = blockIdx.x;
    const int half = blockIdx.y;                 // 0 or 1: which 1024 batches
    const float* src = (blk < N_) ? (trace + (size_t)blk * B_ * D_) : x;
    float* dst = (blk < N_) ? (g_scratch + TR_OFF + (size_t)blk * D_ * B_)
                            : (g_scratch + XT_OFF);
    src += (size_t)half * (B_ / 2) * D_;
    const int t = threadIdx.x;

    for (int ti = 0; ti < B_ / 256; ++ti) {      // 8 tiles of 128 batches
        const float4* s4 = reinterpret_cast<const float4*>(src + (size_t)ti * 128 * D_);
        #pragma unroll
        for (int j = t; j < 512; j += 256) {
            float4 v = s4[j];
            int bb = j >> 2;
            int dd = (j & 3) * 4;
            tile[bb * 17 + dd + 0] = v.x;
            tile[bb * 17 + dd + 1] = v.y;
            tile[bb * 17 + dd + 2] = v.z;
            tile[bb * 17 + dd + 3] = v.w;
        }
        __syncthreads();
        #pragma unroll
        for (int j = t; j < 2048; j += 256) {
            int d  = j >> 7;
            int bb = j & 127;
            dst[(size_t)d * B_ + half * (B_ / 2) + ti * 128 + bb] = tile[bb * 17 + d];
        }
        __syncthreads();
    }
}

// ---------------------------------------------------------------------------
// Layer kernel: block = (node m, batch-tile of 128), 128 threads,
// ONE batch per thread.  8192 warps/layer -> ~40 resident warps/SM at
// <=48 regs.  Gathers streamed in chunks of 16 (high MLP), packed fp32x2
// d-pair accumulation from transposed smem weights.
// ---------------------------------------------------------------------------
__global__ void __launch_bounds__(128, 10) layer_kernel(
    float* __restrict__ out,
    const int* __restrict__ src_node,
    const int* __restrict__ src_feat,
    const float* __restrict__ W,
    const float* __restrict__ bias,
    int l)
{
    const int m = blockIdx.x;
    const int n = l * M_ + m;
    const int t = threadIdx.x;
    const int b = blockIdx.y * 128 + t;          // one batch element

    __shared__ float    sWt[K_ * D_];            // sWt[k*16 + d] = W[n][d][k]
    __shared__ float    sBias[D_];
    __shared__ unsigned sOff[K_];

    #pragma unroll
    for (int i = t; i < D_ * K_; i += 128) {
        int d = i >> 5, k = i & 31;
        sWt[k * D_ + d] = W[(size_t)n * (D_ * K_) + i];
    }
    if (t < D_) sBias[t] = bias[n * D_ + t];
    if (t < K_) {
        int sn = src_node[n * K_ + t];
        int sf = src_feat[n * K_ + t];
        unsigned off;
        if (sn == 0) {
            off = XT_OFF + (unsigned)sf * B_;
        } else if (sn <= l * M_) {
            off = OUT_OFF + ((unsigned)(sn - 1) * D_ + (unsigned)sf) * B_;
        } else {
            off = TR_OFF  + ((unsigned)(sn - 1) * D_ + (unsigned)sf) * B_;
        }
        sOff[t] = off;
    }
    __syncthreads();

    unsigned long long acc[D_ / 2];
    #pragma unroll
    for (int dp = 0; dp < D_ / 2; ++dp)
        acc[dp] = pack2(sBias[2 * dp], sBias[2 * dp + 1]);

    #pragma unroll
    for (int kc = 0; kc < K_ / 16; ++kc) {
        // 16 outstanding coalesced LDG.32 gathers.
        float g[16];
        #pragma unroll
        for (int j = 0; j < 16; ++j)
            g[j] = __ldg(&g_scratch[sOff[16 * kc + j] + (unsigned)b]);

        #pragma unroll
        for (int j = 0; j < 16; ++j) {
            const int k = 16 * kc + j;
            unsigned long long gx = pack2(g[j], g[j]);
            const ulonglong2* wrow = reinterpret_cast<const ulonglong2*>(&sWt[k * D_]);
            #pragma unroll
            for (int q = 0; q < 4; ++q) {        // 4 x LDS.128 broadcast
                ulonglong2 w2 = wrow[q];
                acc[2 * q + 0] = fma2(gx, w2.x, acc[2 * q + 0]);
                acc[2 * q + 1] = fma2(gx, w2.y, acc[2 * q + 1]);
            }
        }
    }

    float a[D_];
    #pragma unroll
    for (int dp = 0; dp < D_ / 2; ++dp) {
        float2 v = unpack2(acc[dp]);
        a[2 * dp]     = fmaxf(v.x, 0.0f);
        a[2 * dp + 1] = fmaxf(v.y, 0.0f);
    }

    // Transposed copy for later-layer gathers (skip on last layer: never read).
    if (l != L_ - 1) {
        float* oT = g_scratch + OUT_OFF + (size_t)n * (D_ * B_);
        #pragma unroll
        for (int d = 0; d < D_; ++d)
            oT[d * B_ + b] = a[d];
    }

    // Final output (N, B, D): 64 B contiguous per thread.
    float* o = out + ((size_t)n * B_ + (size_t)b) * D_;
    #pragma unroll
    for (int d4 = 0; d4 < D_ / 4; ++d4)
        *reinterpret_cast<float4*>(&o[4 * d4]) =
            make_float4(a[4 * d4 + 0], a[4 * d4 + 1], a[4 * d4 + 2], a[4 * d4 + 3]);
}

extern "C" void kernel_launch(void* const* d_in, const int* in_sizes, int n_in,
                              void* d_out, int out_size)
{
    const float* x      = (const float*)d_in[0];
    const float* trace  = (const float*)d_in[1];
    const int*   src_n  = (const int*)d_in[2];
    const int*   src_f  = (const int*)d_in[3];
    const float* W      = (const float*)d_in[4];
    const float* bias   = (const float*)d_in[5];
    float* out = (float*)d_out;

    transpose_kernel<<<dim3(N_ + 1, 2), 256>>>(trace, x);
    for (int l = 0; l < L_; ++l)
        layer_kernel<<<dim3(M_, B_ / 128), 128>>>(out, src_n, src_f, W, bias, l);
}

// round 5
// speedup vs baseline: 1.0105x; 1.0105x over previous
#include <cuda_runtime.h>
#include <cstdint>
#include <cstddef>

#define L_ 8
#define M_ 128
#define K_ 32
#define D_ 16
#define B_ 2048
#define N_ 1024  /* L_*M_ */

#define XT_OFF   0u
#define TR_OFF   ((unsigned)(D_ * B_))
#define OUT_OFF  ((unsigned)(D_ * B_ + N_ * D_ * B_))

static __device__ float g_scratch[(size_t)D_ * B_ + 2ull * N_ * D_ * B_];

// ---- packed fp32x2 helpers (sm_10x only) ----------------------------------
__device__ __forceinline__ unsigned long long fma2(
    unsigned long long a, unsigned long long b, unsigned long long c)
{
    unsigned long long d;
    asm("fma.rn.f32x2 %0, %1, %2, %3;" : "=l"(d) : "l"(a), "l"(b), "l"(c));
    return d;
}
__device__ __forceinline__ unsigned long long pack2(float lo, float hi)
{
    unsigned long long r;
    asm("mov.b64 %0, {%1, %2};" : "=l"(r) : "f"(lo), "f"(hi));
    return r;
}
__device__ __forceinline__ float2 unpack2(unsigned long long v)
{
    float2 r;
    asm("mov.b64 {%0, %1}, %2;" : "=f"(r.x), "=f"(r.y) : "l"(v));
    return r;
}

// ---------------------------------------------------------------------------
// Transpose: block = (node, half-of-B).  One (1024, D) half-tile -> (D, 1024).
// ---------------------------------------------------------------------------
__global__ void __launch_bounds__(256) transpose_kernel(
    const float* __restrict__ trace, const float* __restrict__ x)
{
    __shared__ float tile[128 * 17];
    const int blk  = blockIdx.x;
    const int half = blockIdx.y;
    const float* src = (blk < N_) ? (trace + (size_t)blk * B_ * D_) : x;
    float* dst = (blk < N_) ? (g_scratch + TR_OFF + (size_t)blk * D_ * B_)
                            : (g_scratch + XT_OFF);
    src += (size_t)half * (B_ / 2) * D_;
    const int t = threadIdx.x;

    for (int ti = 0; ti < B_ / 256; ++ti) {
        const float4* s4 = reinterpret_cast<const float4*>(src + (size_t)ti * 128 * D_);
        #pragma unroll
        for (int j = t; j < 512; j += 256) {
            float4 v = s4[j];
            int bb = j >> 2;
            int dd = (j & 3) * 4;
            tile[bb * 17 + dd + 0] = v.x;
            tile[bb * 17 + dd + 1] = v.y;
            tile[bb * 17 + dd + 2] = v.z;
            tile[bb * 17 + dd + 3] = v.w;
        }
        __syncthreads();
        #pragma unroll
        for (int j = t; j < 2048; j += 256) {
            int d  = j >> 7;
            int bb = j & 127;
            dst[(size_t)d * B_ + half * (B_ / 2) + ti * 128 + bb] = tile[bb * 17 + d];
        }
        __syncthreads();
    }
}

// ---------------------------------------------------------------------------
// Layer kernel: 128 threads = 2 warp-coherent d-halves x 64 batch-groups.
// Thread: 4 batches (one LDG.128 gather per k) x 8 d's (2 broadcast LDS.128
// per k).  Double-buffered gather pipeline (4 k in flight).
// Grid (128 nodes, 8 batch-tiles of 256).
// ---------------------------------------------------------------------------
__global__ void __launch_bounds__(128, 6) layer_kernel(
    float* __restrict__ out,
    const int* __restrict__ src_node,
    const int* __restrict__ src_feat,
    const float* __restrict__ W,
    const float* __restrict__ bias,
    int l)
{
    const int m  = blockIdx.x;
    const int n  = l * M_ + m;
    const int t  = threadIdx.x;
    const int h  = t >> 6;                       // d-half (warp-coherent)
    const int bg = t & 63;                       // batch group
    const int b  = blockIdx.y * 256 + bg * 4;    // 4 batches per thread

    __shared__ float    sWt[K_ * D_];            // sWt[k*16 + d] = W[n][d][k]
    __shared__ float    sBias[D_];
    __shared__ unsigned sOff[K_];

    #pragma unroll
    for (int i = t; i < D_ * K_; i += 128) {
        int d = i >> 5, k = i & 31;
        sWt[k * D_ + d] = W[(size_t)n * (D_ * K_) + i];
    }
    if (t < D_) sBias[t] = bias[n * D_ + t];
    if (t < K_) {
        int sn = src_node[n * K_ + t];
        int sf = src_feat[n * K_ + t];
        unsigned off;
        if (sn == 0) {
            off = XT_OFF + (unsigned)sf * B_;
        } else if (sn <= l * M_) {
            off = OUT_OFF + ((unsigned)(sn - 1) * D_ + (unsigned)sf) * B_;
        } else {
            off = TR_OFF  + ((unsigned)(sn - 1) * D_ + (unsigned)sf) * B_;
        }
        sOff[t] = off;
    }
    __syncthreads();

    // acc[i][dp]: batch i, packed d-pair (h*8 + 2dp, h*8 + 2dp + 1)
    unsigned long long acc[4][4];
    {
        unsigned long long bp0 = pack2(sBias[h * 8 + 0], sBias[h * 8 + 1]);
        unsigned long long bp1 = pack2(sBias[h * 8 + 2], sBias[h * 8 + 3]);
        unsigned long long bp2 = pack2(sBias[h * 8 + 4], sBias[h * 8 + 5]);
        unsigned long long bp3 = pack2(sBias[h * 8 + 6], sBias[h * 8 + 7]);
        #pragma unroll
        for (int i = 0; i < 4; ++i) {
            acc[i][0] = bp0; acc[i][1] = bp1; acc[i][2] = bp2; acc[i][3] = bp3;
        }
    }

    // Double-buffered gather pipeline: 4 k's (LDG.128 each) in flight.
    float4 gbuf[2][4];
    #pragma unroll
    for (int j = 0; j < 4; ++j)
        gbuf[0][j] = *reinterpret_cast<const float4*>(&g_scratch[sOff[j] + (unsigned)b]);

    #pragma unroll
    for (int kc = 0; kc < K_ / 4; ++kc) {
        if (kc < K_ / 4 - 1) {
            #pragma unroll
            for (int j = 0; j < 4; ++j)
                gbuf[(kc + 1) & 1][j] = *reinterpret_cast<const float4*>(
                    &g_scratch[sOff[4 * (kc + 1) + j] + (unsigned)b]);
        }
        #pragma unroll
        for (int j = 0; j < 4; ++j) {
            const int k = 4 * kc + j;
            float4 g = gbuf[kc & 1][j];
            const ulonglong2* wrow =
                reinterpret_cast<const ulonglong2*>(&sWt[k * D_ + h * 8]);
            ulonglong2 wa = wrow[0];             // d-pairs 0,1 of this half
            ulonglong2 wb = wrow[1];             // d-pairs 2,3
            unsigned long long g0 = pack2(g.x, g.x);
            unsigned long long g1 = pack2(g.y, g.y);
            unsigned long long g2 = pack2(g.z, g.z);
            unsigned long long g3 = pack2(g.w, g.w);
            acc[0][0] = fma2(g0, wa.x, acc[0][0]);
            acc[0][1] = fma2(g0, wa.y, acc[0][1]);
            acc[0][2] = fma2(g0, wb.x, acc[0][2]);
            acc[0][3] = fma2(g0, wb.y, acc[0][3]);
            acc[1][0] = fma2(g1, wa.x, acc[1][0]);
            acc[1][1] = fma2(g1, wa.y, acc[1][1]);
            acc[1][2] = fma2(g1, wb.x, acc[1][2]);
            acc[1][3] = fma2(g1, wb.y, acc[1][3]);
            acc[2][0] = fma2(g2, wa.x, acc[2][0]);
            acc[2][1] = fma2(g2, wa.y, acc[2][1]);
            acc[2][2] = fma2(g2, wb.x, acc[2][2]);
            acc[2][3] = fma2(g2, wb.y, acc[2][3]);
            acc[3][0] = fma2(g3, wa.x, acc[3][0]);
            acc[3][1] = fma2(g3, wa.y, acc[3][1]);
            acc[3][2] = fma2(g3, wb.x, acc[3][2]);
            acc[3][3] = fma2(g3, wb.y, acc[3][3]);
        }
    }

    // ReLU + unpack: a[i][dd] = batch i, local d index dd (global d = h*8+dd)
    float a[4][8];
    #pragma unroll
    for (int i = 0; i < 4; ++i) {
        #pragma unroll
        for (int dp = 0; dp < 4; ++dp) {
            float2 v = unpack2(acc[i][dp]);
            a[i][2 * dp]     = fmaxf(v.x, 0.0f);
            a[i][2 * dp + 1] = fmaxf(v.y, 0.0f);
        }
    }

    // Transposed copy for later-layer gathers (skip on last layer).
    if (l != L_ - 1) {
        float* oT = g_scratch + OUT_OFF + (size_t)n * (D_ * B_) + (size_t)(h * 8) * B_;
        #pragma unroll
        for (int dd = 0; dd < 8; ++dd)
            *reinterpret_cast<float4*>(&oT[dd * B_ + b]) =
                make_float4(a[0][dd], a[1][dd], a[2][dd], a[3][dd]);
    }

    // Final output (N, B, D): per batch, this thread's 8-d half (two float4).
    float* o = out + ((size_t)n * B_ + (size_t)b) * D_ + h * 8;
    #pragma unroll
    for (int i = 0; i < 4; ++i) {
        *reinterpret_cast<float4*>(&o[i * D_]) =
            make_float4(a[i][0], a[i][1], a[i][2], a[i][3]);
        *reinterpret_cast<float4*>(&o[i * D_ + 4]) =
            make_float4(a[i][4], a[i][5], a[i][6], a[i][7]);
    }
}

extern "C" void kernel_launch(void* const* d_in, const int* in_sizes, int n_in,
                              void* d_out, int out_size)
{
    const float* x      = (const float*)d_in[0];
    const float* trace  = (const float*)d_in[1];
    const int*   src_n  = (const int*)d_in[2];
    const int*   src_f  = (const int*)d_in[3];
    const float* W      = (const float*)d_in[4];
    const float* bias   = (const float*)d_in[5];
    float* out = (float*)d_out;

    transpose_kernel<<<dim3(N_ + 1, 2), 256>>>(trace, x);
    for (int l = 0; l < L_; ++l)
        layer_kernel<<<dim3(M_, B_ / 256), 128>>>(out, src_n, src_f, W, bias, l);
}